// round 15
// baseline (speedup 1.0000x reference)
#include <cuda_runtime.h>

// Problem constants (fixed by reference setup_inputs)
#define C_    128
#define D_    24
#define H_    128
#define W_    128
#define HW_   (H_ * W_)
#define DHW_  (D_ * HW_)
#define OUTH  7
#define OUTD  4
#define SN_   2
#define NBINS (OUTD * OUTH * OUTH)   // 196
#define CG    16                     // channels per block (gridDim.y = 8)
#define TPB   224                    // 7 warps; warp index = bin-row h

#define SCALE_XY 0.125f
#define SCALE_Z  0.25f

// R5 structure (proven 172.8us — survived 9 attack rounds) with the
// channel-pair loop fully unrolled: under the existing 97-reg ceiling
// (launch_bounds 224,3) ptxas may partially software-pipeline adjacent
// iterations using the 80->96 reg slack WITHOUT losing a CTA
// (96*224*3 = 64512 < 65536). Worst case it emits exactly the R5 code.
__global__ __launch_bounds__(TPB, 3)
void roialign3d_kernel(const float* __restrict__ feat,
                       const float* __restrict__ rois,
                       float* __restrict__ out,
                       int R)
{
    const int r    = blockIdx.x;         // roi
    const int cg   = blockIdx.y;         // channel group
    const int h    = threadIdx.x >> 5;   // warp id = output h (0..6)
    const int lane = threadIdx.x & 31;
    // lane -> (w bin, x tap). 28 active lanes; lanes 28..31 mirror w=6 (weight 0).
    const int  wbin   = (lane >> 2) < OUTH ? (lane >> 2) : (OUTH - 1);
    const int  tap    = lane & 3;        // (sample = tap>>1, corner = tap&1)
    const bool active = (lane >> 2) < OUTH;

    // ---- ROI params (uniform) ----
    const float* roi = rois + (size_t)r * 7;
    const int   b  = (int)__ldg(roi + 0);
    const float x1 = __ldg(roi + 1) * SCALE_XY;
    const float y1 = __ldg(roi + 2) * SCALE_XY;
    const float x2 = __ldg(roi + 3) * SCALE_XY;
    const float y2 = __ldg(roi + 4) * SCALE_XY;
    const float z1 = __ldg(roi + 5) * SCALE_Z;
    const float z2 = __ldg(roi + 6) * SCALE_Z;

    const float bw = fmaxf(x2 - x1, 1.0f) * (1.0f / OUTH);
    const float bh = fmaxf(y2 - y1, 1.0f) * (1.0f / OUTH);
    const float bd = fmaxf(z2 - z1, 1.0f) * (1.0f / OUTD);

    // ---- This lane's x tap: offset (clipped in-bounds) + weight (validity folded) ----
    int   xoff;
    float xw;
    {
        const int   s  = tap >> 1;
        float c  = x1 + ((float)wbin + 0.25f + 0.5f * (float)s) * bw;
        float v  = (c > -1.0f && c < (float)W_) ? 1.0f : 0.0f;
        float cc = fminf(fmaxf(c, 0.0f), (float)(W_ - 1));
        int   lo = (int)cc;
        int   hi = (lo < W_ - 1) ? lo + 1 : lo;
        float f  = cc - (float)lo;
        xoff = (tap & 1) ? hi : lo;
        xw   = ((tap & 1) ? f : (1.0f - f)) * v;
        if (!active) xw = 0.0f;
    }

    // ---- 4 y taps for this warp's h (uniform across warp) ----
    int   yoff[4];
    float yw[4];
#pragma unroll
    for (int s = 0; s < SN_; s++) {
        float c  = y1 + ((float)h + 0.25f + 0.5f * (float)s) * bh;
        float v  = (c > -1.0f && c < (float)H_) ? 1.0f : 0.0f;
        float cc = fminf(fmaxf(c, 0.0f), (float)(H_ - 1));
        int   lo = (int)cc;
        int   hi = (lo < H_ - 1) ? lo + 1 : lo;
        float f  = cc - (float)lo;
        yoff[2*s]   = lo * W_;  yw[2*s]   = (1.0f - f) * v;
        yoff[2*s+1] = hi * W_;  yw[2*s+1] = f * v;
    }

    const int c0 = cg * CG;
    const float* pbase = feat + ((size_t)b * C_ + c0) * (size_t)DHW_ + xoff;
    float* obase = out + ((size_t)(r * C_ + c0)) * (size_t)NBINS + h * OUTH + wbin;

    // ---- Loop over d bin-rows ----
    for (int d = 0; d < OUTD; d++) {
        // 4 z taps
        int   zoff[4];
        float zw[4];
#pragma unroll
        for (int s = 0; s < SN_; s++) {
            float c  = z1 + ((float)d + 0.25f + 0.5f * (float)s) * bd;
            float v  = (c > -1.0f && c < (float)D_) ? 1.0f : 0.0f;
            float cc = fminf(fmaxf(c, 0.0f), (float)(D_ - 1));
            int   lo = (int)cc;
            int   hi = (lo < D_ - 1) ? lo + 1 : lo;
            float f  = cc - (float)lo;
            zoff[2*s]   = lo * HW_;  zw[2*s]   = (1.0f - f) * v;
            zoff[2*s+1] = hi * HW_;  zw[2*s+1] = f * v;
        }

        // 16 row offsets + scalar weights (uniform across warp)
        int   rowoff[16];
        float wzy[16];
#pragma unroll
        for (int zt = 0; zt < 4; zt++)
#pragma unroll
            for (int yt = 0; yt < 4; yt++) {
                rowoff[zt * 4 + yt] = zoff[zt] + yoff[yt];
                wzy[zt * 4 + yt]    = zw[zt] * yw[yt];
            }

        float* od = obase + (size_t)d * (OUTH * OUTH);

        // ---- Channel loop, 2 channels at a time (32 independent LDGs),
        //      fully unrolled so ptxas can pipeline across iterations ----
#pragma unroll
        for (int ci = 0; ci < CG; ci += 2) {
            const float* pA = pbase + (size_t)ci * DHW_;
            const float* pB = pA + DHW_;

            float vA[16], vB[16];
#pragma unroll
            for (int i = 0; i < 16; i++) {
                vA[i] = __ldg(pA + rowoff[i]);
                vB[i] = __ldg(pB + rowoff[i]);
            }

            // two partial chains each to shorten the FMA dependency
            float a0 = 0.f, a1 = 0.f, b0 = 0.f, b1 = 0.f;
#pragma unroll
            for (int i = 0; i < 16; i += 2) {
                a0 = fmaf(wzy[i],     vA[i],     a0);
                a1 = fmaf(wzy[i + 1], vA[i + 1], a1);
                b0 = fmaf(wzy[i],     vB[i],     b0);
                b1 = fmaf(wzy[i + 1], vB[i + 1], b1);
            }
            float accA = (a0 + a1) * xw;
            float accB = (b0 + b1) * xw;

            // reduce across the 4 x-taps (lanes 4w..4w+3)
            accA += __shfl_xor_sync(0xFFFFFFFFu, accA, 1);
            accA += __shfl_xor_sync(0xFFFFFFFFu, accA, 2);
            accB += __shfl_xor_sync(0xFFFFFFFFu, accB, 1);
            accB += __shfl_xor_sync(0xFFFFFFFFu, accB, 2);

            if (active && tap == 0) {
                od[(size_t)ci * NBINS]       = accA * 0.125f;  // mean over 8 samples
                od[(size_t)(ci + 1) * NBINS] = accB * 0.125f;
            }
        }
    }
}

extern "C" void kernel_launch(void* const* d_in, const int* in_sizes, int n_in,
                              void* d_out, int out_size)
{
    const float* feat = (const float*)d_in[0];
    const float* rois = (const float*)d_in[1];
    float* out = (float*)d_out;

    const int R = in_sizes[1] / 7;   // 256

    dim3 grid(R, C_ / CG, 1);        // 256 x 8 = 2048 blocks
    dim3 block(TPB, 1, 1);           // 224 threads (7 warps)
    roialign3d_kernel<<<grid, block>>>(feat, rois, out, R);
}

// round 16
// speedup vs baseline: 1.0383x; 1.0383x over previous
#include <cuda_runtime.h>

// Problem constants (fixed by reference setup_inputs)
#define C_    128
#define D_    24
#define H_    128
#define W_    128
#define HW_   (H_ * W_)
#define DHW_  (D_ * HW_)
#define OUTH  7
#define OUTD  4
#define SN_   2
#define NBINS (OUTD * OUTH * OUTH)   // 196
#define CG    16                     // channels per block (gridDim.y = 8)
#define TPB   224                    // 7 warps; warp index = bin-row h

#define SCALE_XY 0.125f
#define SCALE_Z  0.25f

// R5 structure (proven 172.8us) + per-axis tap deduplication: duplicate
// y/z tap offsets (common when bin size < 2px, or at clip boundaries) are
// folded into one tap with summed weight; the folded-away slots keep their
// place in the static 16-slot batch but load under a false predicate
// (@!P LDG: issue slot only, no LSU dispatch, no L1 wavefront).
// Typical effect: ~9 of 16 loads real -> ~40% less L1/LSU work chip-wide.
__global__ __launch_bounds__(TPB, 3)
void roialign3d_kernel(const float* __restrict__ feat,
                       const float* __restrict__ rois,
                       float* __restrict__ out,
                       int R)
{
    const int r    = blockIdx.x;         // roi
    const int cg   = blockIdx.y;         // channel group
    const int h    = threadIdx.x >> 5;   // warp id = output h (0..6)
    const int lane = threadIdx.x & 31;
    // lane -> (w bin, x tap). 28 active lanes; lanes 28..31 mirror w=6 (weight 0).
    const int  wbin   = (lane >> 2) < OUTH ? (lane >> 2) : (OUTH - 1);
    const int  tap    = lane & 3;        // (sample = tap>>1, corner = tap&1)
    const bool active = (lane >> 2) < OUTH;

    // ---- ROI params (uniform) ----
    const float* roi = rois + (size_t)r * 7;
    const int   b  = (int)__ldg(roi + 0);
    const float x1 = __ldg(roi + 1) * SCALE_XY;
    const float y1 = __ldg(roi + 2) * SCALE_XY;
    const float x2 = __ldg(roi + 3) * SCALE_XY;
    const float y2 = __ldg(roi + 4) * SCALE_XY;
    const float z1 = __ldg(roi + 5) * SCALE_Z;
    const float z2 = __ldg(roi + 6) * SCALE_Z;

    const float bw = fmaxf(x2 - x1, 1.0f) * (1.0f / OUTH);
    const float bh = fmaxf(y2 - y1, 1.0f) * (1.0f / OUTH);
    const float bd = fmaxf(z2 - z1, 1.0f) * (1.0f / OUTD);

    // ---- This lane's x tap: offset (clipped in-bounds) + weight (validity folded) ----
    int   xoff;
    float xw;
    {
        const int   s  = tap >> 1;
        float c  = x1 + ((float)wbin + 0.25f + 0.5f * (float)s) * bw;
        float v  = (c > -1.0f && c < (float)W_) ? 1.0f : 0.0f;
        float cc = fminf(fmaxf(c, 0.0f), (float)(W_ - 1));
        int   lo = (int)cc;
        int   hi = (lo < W_ - 1) ? lo + 1 : lo;
        float f  = cc - (float)lo;
        xoff = (tap & 1) ? hi : lo;
        xw   = ((tap & 1) ? f : (1.0f - f)) * v;
        if (!active) xw = 0.0f;
    }

    // ---- 4 y taps for this warp's h + static duplicate-fold ----
    int   yo[4];  float wy[4];  bool ay[4];
#pragma unroll
    for (int s = 0; s < SN_; s++) {
        float c  = y1 + ((float)h + 0.25f + 0.5f * (float)s) * bh;
        float v  = (c > -1.0f && c < (float)H_) ? 1.0f : 0.0f;
        float cc = fminf(fmaxf(c, 0.0f), (float)(H_ - 1));
        int   lo = (int)cc;
        int   hi = (lo < H_ - 1) ? lo + 1 : lo;
        float f  = cc - (float)lo;
        yo[2*s]   = lo * W_;  wy[2*s]   = (1.0f - f) * v;
        yo[2*s+1] = hi * W_;  wy[2*s+1] = f * v;
    }
    ay[0] = ay[1] = ay[2] = ay[3] = true;
    // fold duplicates (static merge network, constant indices only)
    if (yo[1] == yo[0])              { wy[0] += wy[1]; ay[1] = false; }
    if (yo[2] == yo[0])              { wy[0] += wy[2]; ay[2] = false; }
    else if (ay[1] && yo[2] == yo[1]){ wy[1] += wy[2]; ay[2] = false; }
    if (yo[3] == yo[0])              { wy[0] += wy[3]; ay[3] = false; }
    else if (ay[1] && yo[3] == yo[1]){ wy[1] += wy[3]; ay[3] = false; }
    else if (ay[2] && yo[3] == yo[2]){ wy[2] += wy[3]; ay[3] = false; }
#pragma unroll
    for (int i = 0; i < 4; i++) ay[i] = ay[i] && (wy[i] != 0.0f);

    const int c0 = cg * CG;
    const float* pbase = feat + ((size_t)b * C_ + c0) * (size_t)DHW_ + xoff;
    float* obase = out + ((size_t)(r * C_ + c0)) * (size_t)NBINS + h * OUTH + wbin;

    // ---- Loop over d bin-rows ----
    for (int d = 0; d < OUTD; d++) {
        // 4 z taps + static duplicate-fold
        int   zo[4];  float wz[4];  bool az[4];
#pragma unroll
        for (int s = 0; s < SN_; s++) {
            float c  = z1 + ((float)d + 0.25f + 0.5f * (float)s) * bd;
            float v  = (c > -1.0f && c < (float)D_) ? 1.0f : 0.0f;
            float cc = fminf(fmaxf(c, 0.0f), (float)(D_ - 1));
            int   lo = (int)cc;
            int   hi = (lo < D_ - 1) ? lo + 1 : lo;
            float f  = cc - (float)lo;
            zo[2*s]   = lo * HW_;  wz[2*s]   = (1.0f - f) * v;
            zo[2*s+1] = hi * HW_;  wz[2*s+1] = f * v;
        }
        az[0] = az[1] = az[2] = az[3] = true;
        if (zo[1] == zo[0])              { wz[0] += wz[1]; az[1] = false; }
        if (zo[2] == zo[0])              { wz[0] += wz[2]; az[2] = false; }
        else if (az[1] && zo[2] == zo[1]){ wz[1] += wz[2]; az[2] = false; }
        if (zo[3] == zo[0])              { wz[0] += wz[3]; az[3] = false; }
        else if (az[1] && zo[3] == zo[1]){ wz[1] += wz[3]; az[3] = false; }
        else if (az[2] && zo[3] == zo[2]){ wz[2] += wz[3]; az[3] = false; }
#pragma unroll
        for (int i = 0; i < 4; i++) az[i] = az[i] && (wz[i] != 0.0f);

        // 16 slots: offsets, folded weights, activity predicates
        int   rowoff[16];
        float wzy[16];
        bool  act[16];
#pragma unroll
        for (int zt = 0; zt < 4; zt++)
#pragma unroll
            for (int yt = 0; yt < 4; yt++) {
                rowoff[zt * 4 + yt] = zo[zt] + yo[yt];
                wzy[zt * 4 + yt]    = wz[zt] * wy[yt];
                act[zt * 4 + yt]    = az[zt] && ay[yt];
            }

        float* od = obase + (size_t)d * (OUTH * OUTH);

        // ---- Channel loop, 2 channels at a time; inactive slots are
        //      predicated-off LDGs (no LSU/L1 work) ----
        for (int ci = 0; ci < CG; ci += 2) {
            const float* pA = pbase + (size_t)ci * DHW_;
            const float* pB = pA + DHW_;

            float vA[16], vB[16];
#pragma unroll
            for (int i = 0; i < 16; i++) {
                vA[i] = act[i] ? __ldg(pA + rowoff[i]) : 0.0f;
                vB[i] = act[i] ? __ldg(pB + rowoff[i]) : 0.0f;
            }

            // two partial chains each to shorten the FMA dependency
            float a0 = 0.f, a1 = 0.f, b0 = 0.f, b1 = 0.f;
#pragma unroll
            for (int i = 0; i < 16; i += 2) {
                a0 = fmaf(wzy[i],     vA[i],     a0);
                a1 = fmaf(wzy[i + 1], vA[i + 1], a1);
                b0 = fmaf(wzy[i],     vB[i],     b0);
                b1 = fmaf(wzy[i + 1], vB[i + 1], b1);
            }
            float accA = (a0 + a1) * xw;
            float accB = (b0 + b1) * xw;

            // reduce across the 4 x-taps (lanes 4w..4w+3)
            accA += __shfl_xor_sync(0xFFFFFFFFu, accA, 1);
            accA += __shfl_xor_sync(0xFFFFFFFFu, accA, 2);
            accB += __shfl_xor_sync(0xFFFFFFFFu, accB, 1);
            accB += __shfl_xor_sync(0xFFFFFFFFu, accB, 2);

            if (active && tap == 0) {
                od[(size_t)ci * NBINS]       = accA * 0.125f;  // mean over 8 samples
                od[(size_t)(ci + 1) * NBINS] = accB * 0.125f;
            }
        }
    }
}

extern "C" void kernel_launch(void* const* d_in, const int* in_sizes, int n_in,
                              void* d_out, int out_size)
{
    const float* feat = (const float*)d_in[0];
    const float* rois = (const float*)d_in[1];
    float* out = (float*)d_out;

    const int R = in_sizes[1] / 7;   // 256

    dim3 grid(R, C_ / CG, 1);        // 256 x 8 = 2048 blocks
    dim3 block(TPB, 1, 1);           // 224 threads (7 warps)
    roialign3d_kernel<<<grid, block>>>(feat, rois, out, R);
}

// round 17
// speedup vs baseline: 1.3849x; 1.3338x over previous
#include <cuda_runtime.h>

// Problem constants (fixed by reference setup_inputs)
#define C_    128
#define D_    24
#define H_    128
#define W_    128
#define HW_   (H_ * W_)
#define DHW_  (D_ * HW_)
#define OUTH  7
#define OUTD  4
#define SN_   2
#define NBINS (OUTD * OUTH * OUTH)   // 196
#define CG    16                     // channels per block (gridDim.y = 8)
#define TPB   224                    // 7 warps; warp index = bin-row h

#define SCALE_XY 0.125f
#define SCALE_Z  0.25f

// R5 kernel (champion, 172.8us, survived 11 structural attack rounds)
// with ONE change: output stores use __stcs (evict-first streaming hint).
// Output is write-once/never-read; keeping its lines out of the L2 working
// set preserves more of the feature tensor in L2 (the reuse that holds DRAM
// traffic at ~425MB). Body is otherwise byte-identical to R5.
__global__ __launch_bounds__(TPB, 3)
void roialign3d_kernel(const float* __restrict__ feat,
                       const float* __restrict__ rois,
                       float* __restrict__ out,
                       int R)
{
    const int r    = blockIdx.x;         // roi
    const int cg   = blockIdx.y;         // channel group
    const int h    = threadIdx.x >> 5;   // warp id = output h (0..6)
    const int lane = threadIdx.x & 31;
    // lane -> (w bin, x tap). 28 active lanes; lanes 28..31 mirror w=6 (weight 0).
    const int  wbin   = (lane >> 2) < OUTH ? (lane >> 2) : (OUTH - 1);
    const int  tap    = lane & 3;        // (sample = tap>>1, corner = tap&1)
    const bool active = (lane >> 2) < OUTH;

    // ---- ROI params (uniform) ----
    const float* roi = rois + (size_t)r * 7;
    const int   b  = (int)__ldg(roi + 0);
    const float x1 = __ldg(roi + 1) * SCALE_XY;
    const float y1 = __ldg(roi + 2) * SCALE_XY;
    const float x2 = __ldg(roi + 3) * SCALE_XY;
    const float y2 = __ldg(roi + 4) * SCALE_XY;
    const float z1 = __ldg(roi + 5) * SCALE_Z;
    const float z2 = __ldg(roi + 6) * SCALE_Z;

    const float bw = fmaxf(x2 - x1, 1.0f) * (1.0f / OUTH);
    const float bh = fmaxf(y2 - y1, 1.0f) * (1.0f / OUTH);
    const float bd = fmaxf(z2 - z1, 1.0f) * (1.0f / OUTD);

    // ---- This lane's x tap: offset (clipped in-bounds) + weight (validity folded) ----
    int   xoff;
    float xw;
    {
        const int   s  = tap >> 1;
        float c  = x1 + ((float)wbin + 0.25f + 0.5f * (float)s) * bw;
        float v  = (c > -1.0f && c < (float)W_) ? 1.0f : 0.0f;
        float cc = fminf(fmaxf(c, 0.0f), (float)(W_ - 1));
        int   lo = (int)cc;
        int   hi = (lo < W_ - 1) ? lo + 1 : lo;
        float f  = cc - (float)lo;
        xoff = (tap & 1) ? hi : lo;
        xw   = ((tap & 1) ? f : (1.0f - f)) * v;
        if (!active) xw = 0.0f;
    }

    // ---- 4 y taps for this warp's h (uniform across warp) ----
    int   yoff[4];
    float yw[4];
#pragma unroll
    for (int s = 0; s < SN_; s++) {
        float c  = y1 + ((float)h + 0.25f + 0.5f * (float)s) * bh;
        float v  = (c > -1.0f && c < (float)H_) ? 1.0f : 0.0f;
        float cc = fminf(fmaxf(c, 0.0f), (float)(H_ - 1));
        int   lo = (int)cc;
        int   hi = (lo < H_ - 1) ? lo + 1 : lo;
        float f  = cc - (float)lo;
        yoff[2*s]   = lo * W_;  yw[2*s]   = (1.0f - f) * v;
        yoff[2*s+1] = hi * W_;  yw[2*s+1] = f * v;
    }

    const int c0 = cg * CG;
    const float* pbase = feat + ((size_t)b * C_ + c0) * (size_t)DHW_ + xoff;
    float* obase = out + ((size_t)(r * C_ + c0)) * (size_t)NBINS + h * OUTH + wbin;

    // ---- Loop over d bin-rows ----
    for (int d = 0; d < OUTD; d++) {
        // 4 z taps
        int   zoff[4];
        float zw[4];
#pragma unroll
        for (int s = 0; s < SN_; s++) {
            float c  = z1 + ((float)d + 0.25f + 0.5f * (float)s) * bd;
            float v  = (c > -1.0f && c < (float)D_) ? 1.0f : 0.0f;
            float cc = fminf(fmaxf(c, 0.0f), (float)(D_ - 1));
            int   lo = (int)cc;
            int   hi = (lo < D_ - 1) ? lo + 1 : lo;
            float f  = cc - (float)lo;
            zoff[2*s]   = lo * HW_;  zw[2*s]   = (1.0f - f) * v;
            zoff[2*s+1] = hi * HW_;  zw[2*s+1] = f * v;
        }

        // 16 row offsets + scalar weights (uniform across warp)
        int   rowoff[16];
        float wzy[16];
#pragma unroll
        for (int zt = 0; zt < 4; zt++)
#pragma unroll
            for (int yt = 0; yt < 4; yt++) {
                rowoff[zt * 4 + yt] = zoff[zt] + yoff[yt];
                wzy[zt * 4 + yt]    = zw[zt] * yw[yt];
            }

        float* od = obase + (size_t)d * (OUTH * OUTH);

        // ---- Channel loop, 2 channels at a time (32 independent LDGs) ----
        for (int ci = 0; ci < CG; ci += 2) {
            const float* pA = pbase + (size_t)ci * DHW_;
            const float* pB = pA + DHW_;

            float vA[16], vB[16];
#pragma unroll
            for (int i = 0; i < 16; i++) {
                vA[i] = __ldg(pA + rowoff[i]);
                vB[i] = __ldg(pB + rowoff[i]);
            }

            // two partial chains each to shorten the FMA dependency
            float a0 = 0.f, a1 = 0.f, b0 = 0.f, b1 = 0.f;
#pragma unroll
            for (int i = 0; i < 16; i += 2) {
                a0 = fmaf(wzy[i],     vA[i],     a0);
                a1 = fmaf(wzy[i + 1], vA[i + 1], a1);
                b0 = fmaf(wzy[i],     vB[i],     b0);
                b1 = fmaf(wzy[i + 1], vB[i + 1], b1);
            }
            float accA = (a0 + a1) * xw;
            float accB = (b0 + b1) * xw;

            // reduce across the 4 x-taps (lanes 4w..4w+3)
            accA += __shfl_xor_sync(0xFFFFFFFFu, accA, 1);
            accA += __shfl_xor_sync(0xFFFFFFFFu, accA, 2);
            accB += __shfl_xor_sync(0xFFFFFFFFu, accB, 1);
            accB += __shfl_xor_sync(0xFFFFFFFFu, accB, 2);

            if (active && tap == 0) {
                // streaming stores: output is never re-read; keep its lines
                // from evicting the feature working set in L2
                __stcs(od + (size_t)ci * NBINS,       accA * 0.125f);
                __stcs(od + (size_t)(ci + 1) * NBINS, accB * 0.125f);
            }
        }
    }
}

extern "C" void kernel_launch(void* const* d_in, const int* in_sizes, int n_in,
                              void* d_out, int out_size)
{
    const float* feat = (const float*)d_in[0];
    const float* rois = (const float*)d_in[1];
    float* out = (float*)d_out;

    const int R = in_sizes[1] / 7;   // 256

    dim3 grid(R, C_ / CG, 1);        // 256 x 8 = 2048 blocks
    dim3 block(TPB, 1, 1);           // 224 threads (7 warps)
    roialign3d_kernel<<<grid, block>>>(feat, rois, out, R);
}